// round 15
// baseline (speedup 1.0000x reference)
#include <cuda_runtime.h>
#include <math.h>

#define BATCH 4
#define SEQ   2048
#define EMB   256
#define HEADS 8
#define HDIM  32
#define KSEL  204        /* int(2048*0.1) */
#define KSEL_PAD 208

#define KC 8
#define BM 128
#define BN 128
#define PAD_LD 132       /* 132 floats = 528B, 16B-aligned rows, conflict-free */
#define SBUF (KC * PAD_LD)

#define SCORES_CTAS (136 * BATCH)      /* 544 */
#define QKV_CTAS    (6 * (BATCH * SEQ / BM))  /* 384 */

/* ------------ scratch (no allocations allowed) ------------ */
__device__ float g_scores[(size_t)BATCH * SEQ * SEQ];   /* 67 MB */
__device__ int   g_idx[BATCH * SEQ * KSEL];
__device__ float g_q[(size_t)BATCH * SEQ * EMB];
__device__ float g_k[(size_t)BATCH * SEQ * EMB];
__device__ float g_v[(size_t)BATCH * SEQ * EMB];
__device__ float g_ctx[(size_t)BATCH * SEQ * EMB];

/* ------------ fast exp on the FMA pipe (avoids MUFU) ------------ */
__device__ __forceinline__ float fexp(float x) {
    float y = x * 1.4426950408889634f;
    if (y < -126.0f) return 0.0f;
    float n = floorf(y);
    float f = y - n;
    float p = 1.33988744e-3f;
    p = fmaf(p, f, 9.61843735e-3f);
    p = fmaf(p, f, 5.55033250e-2f);
    p = fmaf(p, f, 2.40226448e-1f);
    p = fmaf(p, f, 6.93147202e-1f);
    p = fmaf(p, f, 1.0f);
    return p * __int_as_float(((int)n + 127) << 23);
}

/* full-warp fp32 sum via butterfly shuffles (no fp32 REDUX on sm_103) */
__device__ __forceinline__ float warp_sum(float v) {
#pragma unroll
    for (int o = 16; o; o >>= 1) v += __shfl_xor_sync(0xffffffffu, v, o);
    return v;
}

/* ------------ 128x128x8 double-buffered fp32 mainloop (round-8 proven) ------- */
__device__ __forceinline__ void gemm_mainloop(
    const float* __restrict__ A, const float* __restrict__ B, int K,
    float (&acc)[8][8], float* sa, float* sb)
{
    int tid = threadIdx.x;
    int tx = tid & 15, ty = tid >> 4;
    int lr = tid >> 1;              /* 0..127 */
    int lk = (tid & 1) * 4;         /* 0 or 4 */
    const float* ap = A + (size_t)lr * K + lk;
    const float* bp = B + (size_t)lr * K + lk;

    /* preload chunk 0 */
    {
        float4 av = *(const float4*)ap;
        float4 bv = *(const float4*)bp;
        sa[(lk + 0) * PAD_LD + lr] = av.x; sa[(lk + 1) * PAD_LD + lr] = av.y;
        sa[(lk + 2) * PAD_LD + lr] = av.z; sa[(lk + 3) * PAD_LD + lr] = av.w;
        sb[(lk + 0) * PAD_LD + lr] = bv.x; sb[(lk + 1) * PAD_LD + lr] = bv.y;
        sb[(lk + 2) * PAD_LD + lr] = bv.z; sb[(lk + 3) * PAD_LD + lr] = bv.w;
    }
    __syncthreads();

    int buf = 0;
    int nch = K / KC;
    for (int ch = 0; ch < nch; ch++) {
        float4 anx, bnx;
        bool more = (ch + 1 < nch);
        if (more) {
            anx = *(const float4*)(ap + (ch + 1) * KC);
            bnx = *(const float4*)(bp + (ch + 1) * KC);
        }
        const float* ca = sa + buf * SBUF;
        const float* cb = sb + buf * SBUF;
#pragma unroll
        for (int k = 0; k < KC; k++) {
            float4 a0 = *(const float4*)(ca + k * PAD_LD + ty * 4);
            float4 a1 = *(const float4*)(ca + k * PAD_LD + 64 + ty * 4);
            float4 b0 = *(const float4*)(cb + k * PAD_LD + tx * 4);
            float4 b1 = *(const float4*)(cb + k * PAD_LD + 64 + tx * 4);
            float ar[8] = {a0.x, a0.y, a0.z, a0.w, a1.x, a1.y, a1.z, a1.w};
            float br[8] = {b0.x, b0.y, b0.z, b0.w, b1.x, b1.y, b1.z, b1.w};
#pragma unroll
            for (int i = 0; i < 8; i++)
#pragma unroll
                for (int j = 0; j < 8; j++)
                    acc[i][j] = fmaf(ar[i], br[j], acc[i][j]);
        }
        if (more) {
            int nb = buf ^ 1;
            float* na = sa + nb * SBUF;
            float* nbf = sb + nb * SBUF;
            na[(lk + 0) * PAD_LD + lr] = anx.x; na[(lk + 1) * PAD_LD + lr] = anx.y;
            na[(lk + 2) * PAD_LD + lr] = anx.z; na[(lk + 3) * PAD_LD + lr] = anx.w;
            nbf[(lk + 0) * PAD_LD + lr] = bnx.x; nbf[(lk + 1) * PAD_LD + lr] = bnx.y;
            nbf[(lk + 2) * PAD_LD + lr] = bnx.z; nbf[(lk + 3) * PAD_LD + lr] = bnx.w;
            __syncthreads();
            buf = nb;
        }
    }
}

__device__ __forceinline__ int frag_r(int ty, int i) {
    return (i < 4) ? (ty * 4 + i) : (64 + ty * 4 + i - 4);
}

/* ------------ stage1: scores upper-tri tiles + qkv projection, one launch ---- */
/* bx < 544: scores tile (z = bx/136, tri-decode bx%136).                       */
/* bx >= 544: qkv tile (xs = rem%6: seg=xs>>1, colblk=xs&1; rowblk = rem/6).    */
__global__ __launch_bounds__(256) void stage1_kernel(
    const float* __restrict__ x,
    const float* __restrict__ Wq, const float* __restrict__ Wk, const float* __restrict__ Wv,
    const float* __restrict__ bq, const float* __restrict__ bk, const float* __restrict__ bv,
    float* __restrict__ scores,
    float* __restrict__ q, float* __restrict__ k, float* __restrict__ v)
{
    __shared__ float sa[2 * SBUF];
    __shared__ float sb[2 * SBUF];

    int bx = blockIdx.x;
    int tx = threadIdx.x & 15, ty = threadIdx.x >> 4;

    if (bx < SCORES_CTAS) {
        int z = bx / 136;
        int t = bx - z * 136;
        int i = 0, rem = SEQ / BM;
        while (t >= rem) { t -= rem; rem--; i++; }
        int j = i + t;

        const float* xb = x + (size_t)z * SEQ * EMB;
        float* Cb = scores + (size_t)z * SEQ * SEQ;
        int row0 = i * BM, col0 = j * BN;

        float acc[8][8] = {};
        gemm_mainloop(xb + (size_t)row0 * EMB, xb + (size_t)col0 * EMB, EMB, acc, sa, sb);

#pragma unroll
        for (int ii = 0; ii < 8; ii++) {
            int r = row0 + frag_r(ty, ii);
            float4 o0 = {acc[ii][0] * 0.0625f, acc[ii][1] * 0.0625f,
                         acc[ii][2] * 0.0625f, acc[ii][3] * 0.0625f};
            float4 o1 = {acc[ii][4] * 0.0625f, acc[ii][5] * 0.0625f,
                         acc[ii][6] * 0.0625f, acc[ii][7] * 0.0625f};
            *(float4*)(Cb + (size_t)r * SEQ + col0 + tx * 4) = o0;
            *(float4*)(Cb + (size_t)r * SEQ + col0 + 64 + tx * 4) = o1;
        }
    } else {
        int b2 = bx - SCORES_CTAS;
        int xs = b2 % 6;
        int rowb = b2 / 6;
        int seg = xs >> 1;
        const float* W    = (seg == 0) ? Wq : (seg == 1) ? Wk : Wv;
        const float* bias = (seg == 0) ? bq : (seg == 1) ? bk : bv;
        float*       out  = (seg == 0) ? q  : (seg == 1) ? k  : v;
        int col0 = (xs & 1) * BN;
        int row0 = rowb * BM;

        float acc[8][8] = {};
        gemm_mainloop(x + (size_t)row0 * EMB, W + (size_t)col0 * EMB, EMB, acc, sa, sb);

        float4 bb0 = *(const float4*)(bias + col0 + tx * 4);
        float4 bb1 = *(const float4*)(bias + col0 + 64 + tx * 4);
        float bl[8] = {bb0.x, bb0.y, bb0.z, bb0.w, bb1.x, bb1.y, bb1.z, bb1.w};

#pragma unroll
        for (int ii = 0; ii < 8; ii++) {
            int r = row0 + frag_r(ty, ii);
            float4 o0 = {acc[ii][0] + bl[0], acc[ii][1] + bl[1], acc[ii][2] + bl[2], acc[ii][3] + bl[3]};
            float4 o1 = {acc[ii][4] + bl[4], acc[ii][5] + bl[5], acc[ii][6] + bl[6], acc[ii][7] + bl[7]};
            *(float4*)(out + (size_t)r * EMB + col0 + tx * 4) = o0;
            *(float4*)(out + (size_t)r * EMB + col0 + 64 + tx * 4) = o1;
        }
    }
}

/* ------------ C = alpha*A.B^T + bias (out projection) ------------------------ */
__global__ __launch_bounds__(256) void gemm_abt(
    const float* __restrict__ A, const float* __restrict__ B,
    float* __restrict__ C, const float* __restrict__ bias,
    int N, int K, float alpha,
    size_t sA, size_t sB, size_t sC)
{
    A += (size_t)blockIdx.z * sA;
    B += (size_t)blockIdx.z * sB;
    C += (size_t)blockIdx.z * sC;

    __shared__ float sa[2 * SBUF];
    __shared__ float sb[2 * SBUF];

    int tid = threadIdx.x;
    int tx = tid & 15, ty = tid >> 4;
    int row0 = blockIdx.y * BM, col0 = blockIdx.x * BN;

    float acc[8][8] = {};
    gemm_mainloop(A + (size_t)row0 * K, B + (size_t)col0 * K, K, acc, sa, sb);

    float bl[8] = {};
    if (bias) {
        float4 bb0 = *(const float4*)(bias + col0 + tx * 4);
        float4 bb1 = *(const float4*)(bias + col0 + 64 + tx * 4);
        bl[0] = bb0.x; bl[1] = bb0.y; bl[2] = bb0.z; bl[3] = bb0.w;
        bl[4] = bb1.x; bl[5] = bb1.y; bl[6] = bb1.z; bl[7] = bb1.w;
    }

#pragma unroll
    for (int i = 0; i < 8; i++) {
        int r = row0 + frag_r(ty, i);
        float4 o0, o1;
        o0.x = fmaf(alpha, acc[i][0], bl[0]);
        o0.y = fmaf(alpha, acc[i][1], bl[1]);
        o0.z = fmaf(alpha, acc[i][2], bl[2]);
        o0.w = fmaf(alpha, acc[i][3], bl[3]);
        o1.x = fmaf(alpha, acc[i][4], bl[4]);
        o1.y = fmaf(alpha, acc[i][5], bl[5]);
        o1.z = fmaf(alpha, acc[i][6], bl[6]);
        o1.w = fmaf(alpha, acc[i][7], bl[7]);
        *(float4*)(C + (size_t)r * N + col0 + tx * 4) = o0;
        *(float4*)(C + (size_t)r * N + col0 + 64 + tx * 4) = o1;
    }
}

/* ------------ mirror lower triangle via smem transpose (coalesced both ways) - */
__global__ __launch_bounds__(256) void mirror_kernel(float* __restrict__ C)
{
    __shared__ float ts[64 * 65];

    int p = blockIdx.x >> 2, sub = blockIdx.x & 3;
    int I = 1;
    while (p >= I) { p -= I; I++; }
    int J = p;                          /* J < I */

    float* Cb = C + (size_t)blockIdx.z * SEQ * SEQ;
    int dr = I * BM + (sub >> 1) * 64;  /* dest 64-tile origin (lower tri) */
    int dc = J * BM + (sub & 1) * 64;

    int tx = threadIdx.x & 15, ty = threadIdx.x >> 4;

#pragma unroll
    for (int q = 0; q < 4; q++) {
        int r = ty + q * 16;
        float4 s = *(const float4*)(Cb + (size_t)(dc + r) * SEQ + dr + tx * 4);
        ts[(tx * 4 + 0) * 65 + r] = s.x;
        ts[(tx * 4 + 1) * 65 + r] = s.y;
        ts[(tx * 4 + 2) * 65 + r] = s.z;
        ts[(tx * 4 + 3) * 65 + r] = s.w;
    }
    __syncthreads();

#pragma unroll
    for (int q = 0; q < 4; q++) {
        int j = ty + q * 16;
        float4 o;
        o.x = ts[j * 65 + tx * 4 + 0];
        o.y = ts[j * 65 + tx * 4 + 1];
        o.z = ts[j * 65 + tx * 4 + 2];
        o.w = ts[j * 65 + tx * 4 + 3];
        *(float4*)(Cb + (size_t)(dr + j) * SEQ + dc + tx * 4) = o;
    }
}

/* ------------ exact per-row top-k v2: register keys, warp-aggregated hist ---- */
__global__ __launch_bounds__(256) void topk_kernel(
    const float* __restrict__ scores, int* __restrict__ idx)
{
    int row = blockIdx.x;                 /* 0..8191 */
    int tid = threadIdx.x;
    int lane = tid & 31;
    __shared__ unsigned int hist[256];
    __shared__ unsigned int bc[2];
    __shared__ unsigned int thcnt[256];
    __shared__ unsigned int cnt;

    const float* srow = scores + (size_t)row * SEQ;
    int base = tid * 8;
    unsigned int key[8];
    {
        float4 f0 = *(const float4*)(srow + base);
        float4 f1 = *(const float4*)(srow + base + 4);
        float fv[8] = {f0.x, f0.y, f0.z, f0.w, f1.x, f1.y, f1.z, f1.w};
#pragma unroll
        for (int e = 0; e < 8; e++) {
            unsigned int b = __float_as_uint(fv[e]);
            key[e] = b ^ ((b & 0x80000000u) ? 0xFFFFFFFFu : 0x80000000u);
        }
    }
    if (tid == 0) cnt = 0;

    unsigned int remaining = KSEL;
    unsigned int prefix = 0;

#pragma unroll
    for (int shift = 24; shift >= 0; shift -= 8) {
        unsigned int himask = (shift == 24) ? 0u : (0xFFFFFFFFu << (shift + 8));
        hist[tid] = 0;
        __syncthreads();
        /* histogram with warp-aggregated atomics (hot exponent bins) */
#pragma unroll
        for (int e = 0; e < 8; e++) {
            bool valid = (key[e] & himask) == prefix;
            unsigned int bin = (key[e] >> shift) & 255u;
            unsigned int mk = __match_any_sync(0xffffffffu, valid ? bin : 0x400u);
            if (valid) {
                if (lane == __ffs(mk) - 1)
                    atomicAdd(&hist[bin], (unsigned int)__popc(mk));
            }
        }
        __syncthreads();
        /* warp-0 suffix-scan bucket select: lane owns bins [lane*8, lane*8+8) */
        if (tid < 32) {
            unsigned int h[8];
            unsigned int t = 0;
#pragma unroll
            for (int j2 = 0; j2 < 8; j2++) { h[j2] = hist[tid * 8 + j2]; t += h[j2]; }
            unsigned int s = t;                    /* inclusive cross-lane suffix */
#pragma unroll
            for (int o = 1; o < 32; o <<= 1) {
                unsigned int vv = __shfl_down_sync(0xffffffffu, s, o);
                if (lane + o < 32) s += vv;
            }
            unsigned int run = s - t;              /* S[(lane+1)*8] */
#pragma unroll
            for (int j2 = 7; j2 >= 0; j2--) {
                unsigned int Sb = run + h[j2];     /* S[bin], run = S[bin+1] */
                if (Sb >= remaining && run < remaining) {
                    bc[0] = prefix | ((unsigned int)(tid * 8 + j2) << shift);
                    bc[1] = remaining - run;
                }
                run = Sb;
            }
        }
        __syncthreads();
        prefix = bc[0];
        remaining = bc[1];
        __syncthreads();
    }

    unsigned int T = prefix;                    /* exact k-th largest key */
    unsigned int ties_allowed = remaining;
    unsigned int gbase = KSEL - remaining;

    /* strictly greater: ballot-compacted, one atomic per warp per slot */
#pragma unroll
    for (int e = 0; e < 8; e++) {
        unsigned int bal = __ballot_sync(0xffffffffu, key[e] > T);
        if (bal) {
            int leader = __ffs(bal) - 1;
            unsigned int slotbase = 0;
            if (lane == leader)
                slotbase = atomicAdd(&cnt, (unsigned int)__popc(bal));
            slotbase = __shfl_sync(0xffffffffu, slotbase, leader);
            if (key[e] > T) {
                unsigned int rank = __popc(bal & ((1u << lane) - 1u));
                idx[(size_t)row * KSEL + slotbase + rank] = base + e;
            }
        }
    }

    /* ties: blocked ownership -> ascending index order (proven scan) */
    unsigned int local = 0;
#pragma unroll
    for (int i = 0; i < 8; i++) if (key[i] == T) local++;
    thcnt[tid] = local;
    for (int off = 1; off < 256; off <<= 1) {
        __syncthreads();
        unsigned int vv = (tid >= off) ? thcnt[tid - off] : 0u;
        __syncthreads();
        thcnt[tid] += vv;
    }
    __syncthreads();
    unsigned int r = thcnt[tid] - local;
#pragma unroll
    for (int i = 0; i < 8; i++) {
        if (key[i] == T) {
            if (r < ties_allowed)
                idx[(size_t)row * KSEL + gbase + r] = base + i;
            r++;
        }
    }
}

/* ------------ fused sparse attention v4 (round-11 version, unchanged) -------- */
__global__ __launch_bounds__(256) void sparse_attn_kernel(
    const float* __restrict__ q, const float* __restrict__ k,
    const float* __restrict__ v, const int* __restrict__ idx,
    float* __restrict__ ctx, float* __restrict__ attn_out)
{
    int row = blockIdx.x;          /* b*SEQ + s */
    int b = row >> 11;
    int tid = threadIdx.x;
    int warp = tid >> 5, lane = tid & 31;

    __shared__ alignas(16) float qs[EMB];
    __shared__ alignas(16) int   sidx[KSEL_PAD];
    __shared__ alignas(16) float lg[HEADS][KSEL_PAD];
    __shared__ alignas(16) float rowbuf[SEQ];

    qs[tid] = q[(size_t)row * EMB + tid];
    if (tid < KSEL) sidx[tid] = idx[(size_t)row * KSEL + tid];
    __syncthreads();

    float4 q0 = *(const float4*)&qs[lane * 4];
    float4 q1 = *(const float4*)&qs[128 + lane * 4];

    const float* kb = k + (size_t)b * SEQ * EMB;
    int h_lo = lane >> 3;
    int h_hi = 4 + (lane >> 3);
    for (int j = warp; j < KSEL; j += 8) {
        const float* kr = kb + (size_t)sidx[j] * EMB;
        float4 k0 = *(const float4*)(kr + lane * 4);
        float4 k1 = *(const float4*)(kr + 128 + lane * 4);
        float s0 = k0.x * q0.x + k0.y * q0.y + k0.z * q0.z + k0.w * q0.w;
        float s1 = k1.x * q1.x + k1.y * q1.y + k1.z * q1.z + k1.w * q1.w;
#pragma unroll
        for (int o = 1; o < 8; o <<= 1) {
            s0 += __shfl_xor_sync(0xffffffffu, s0, o);
            s1 += __shfl_xor_sync(0xffffffffu, s1, o);
        }
        if ((lane & 7) == 0) {
            lg[h_lo][j] = s0 * 0.17677669529663687f;
            lg[h_hi][j] = s1 * 0.17677669529663687f;
        }
    }
    __syncthreads();

    {
        int h = warp;
        float m = -1e30f;
        for (int j = lane; j < KSEL; j += 32) m = fmaxf(m, lg[h][j]);
#pragma unroll
        for (int o = 16; o; o >>= 1) m = fmaxf(m, __shfl_xor_sync(0xffffffffu, m, o));
        float s = 0.f;
        for (int j = lane; j < KSEL; j += 32) {
            float e = fexp(lg[h][j] - m);
            lg[h][j] = e;
            s += e;
        }
        s = warp_sum(s);
        float inv = 1.f / s;
        for (int j = lane; j < KSEL; j += 32) lg[h][j] *= inv;
    }
    __syncthreads();

    {
        int hh = warp;
        const float* vb = v + (size_t)b * SEQ * EMB + tid;
        const float4* lg4 = (const float4*)&lg[hh][0];
        const int4*   sx4 = (const int4*)sidx;
        float a0 = 0.f, a1 = 0.f, a2 = 0.f, a3 = 0.f;
#pragma unroll 4
        for (int j4 = 0; j4 < KSEL / 4; j4++) {
            float4 p = lg4[j4];
            int4   t = sx4[j4];
            a0 = fmaf(p.x, vb[(size_t)t.x * EMB], a0);
            a1 = fmaf(p.y, vb[(size_t)t.y * EMB], a1);
            a2 = fmaf(p.z, vb[(size_t)t.z * EMB], a2);
            a3 = fmaf(p.w, vb[(size_t)t.w * EMB], a3);
        }
        ctx[(size_t)row * EMB + tid] = (a0 + a1) + (a2 + a3);
    }

    for (int t0 = tid; t0 < SEQ; t0 += 256) rowbuf[t0] = 0.f;
    __syncthreads();
    if (tid < KSEL) {
        float pm = 0.f;
#pragma unroll
        for (int hh = 0; hh < HEADS; hh++) pm += lg[hh][tid];
        rowbuf[sidx[tid]] = pm * 0.125f;
    }
    __syncthreads();
    float4* dst = (float4*)(attn_out + (size_t)row * SEQ);
    const float4* src = (const float4*)rowbuf;
    for (int t0 = tid; t0 < SEQ / 4; t0 += 256) dst[t0] = src[t0];
}

/* ------------ launch ------------ */
extern "C" void kernel_launch(void* const* d_in, const int* in_sizes, int n_in,
                              void* d_out, int out_size)
{
    const float* x  = (const float*)d_in[0];
    const float* Wq = (const float*)d_in[1];
    const float* bq = (const float*)d_in[2];
    const float* Wk = (const float*)d_in[3];
    const float* bk = (const float*)d_in[4];
    const float* Wv = (const float*)d_in[5];
    const float* bv = (const float*)d_in[6];
    const float* Wo = (const float*)d_in[7];
    const float* bo = (const float*)d_in[8];

    float* out  = (float*)d_out;
    float* attn = out + (size_t)BATCH * SEQ * EMB;

    float *scores, *q, *k, *v, *ctx;
    int* idx;
    cudaGetSymbolAddress((void**)&scores, g_scores);
    cudaGetSymbolAddress((void**)&idx,    g_idx);
    cudaGetSymbolAddress((void**)&q,      g_q);
    cudaGetSymbolAddress((void**)&k,      g_k);
    cudaGetSymbolAddress((void**)&v,      g_v);
    cudaGetSymbolAddress((void**)&ctx,    g_ctx);

    /* 1. scores upper-tri (544 CTAs) + qkv projections (384 CTAs), one launch */
    stage1_kernel<<<SCORES_CTAS + QKV_CTAS, 256>>>(
        x, Wq, Wk, Wv, bq, bk, bv, scores, q, k, v);

    /* 2. mirror lower triangle via coalesced smem transpose */
    mirror_kernel<<<dim3(480, 1, BATCH), 256>>>(scores);

    /* 3. exact top-k index selection per row */
    topk_kernel<<<BATCH * SEQ, 256>>>(scores, idx);

    /* 4. fused sparse attention + attn_weights output */
    sparse_attn_kernel<<<BATCH * SEQ, 256>>>(q, k, v, idx, ctx, attn);

    /* 5. out = ctx @ Wo^T + bo */
    gemm_abt<<<dim3(EMB / BN, (BATCH * SEQ) / BM, 1), 256>>>(
        ctx, Wo, out, bo, EMB, EMB, 1.0f, 0, 0, 0);
}

// round 16
// speedup vs baseline: 1.6202x; 1.6202x over previous
#include <cuda_runtime.h>
#include <math.h>

#define BATCH 4
#define SEQ   2048
#define EMB   256
#define HEADS 8
#define HDIM  32
#define KSEL  204        /* int(2048*0.1) */
#define KSEL_PAD 208

#define KC 8
#define BM 128
#define BN 128
#define PAD_LD 132       /* 132 floats = 528B, 16B-aligned rows, conflict-free */
#define SBUF (KC * PAD_LD)

/* ------------ scratch (no allocations allowed) ------------ */
__device__ float g_scores[(size_t)BATCH * SEQ * SEQ];   /* 67 MB */
__device__ int   g_idx[BATCH * SEQ * KSEL];
__device__ float g_q[(size_t)BATCH * SEQ * EMB];
__device__ float g_k[(size_t)BATCH * SEQ * EMB];
__device__ float g_v[(size_t)BATCH * SEQ * EMB];
__device__ float g_ctx[(size_t)BATCH * SEQ * EMB];

/* ------------ fast exp on the FMA pipe (avoids MUFU) ------------ */
__device__ __forceinline__ float fexp(float x) {
    float y = x * 1.4426950408889634f;
    if (y < -126.0f) return 0.0f;
    float n = floorf(y);
    float f = y - n;
    float p = 1.33988744e-3f;
    p = fmaf(p, f, 9.61843735e-3f);
    p = fmaf(p, f, 5.55033250e-2f);
    p = fmaf(p, f, 2.40226448e-1f);
    p = fmaf(p, f, 6.93147202e-1f);
    p = fmaf(p, f, 1.0f);
    return p * __int_as_float(((int)n + 127) << 23);
}

/* full-warp fp32 sum via butterfly shuffles (no fp32 REDUX on sm_103) */
__device__ __forceinline__ float warp_sum(float v) {
#pragma unroll
    for (int o = 16; o; o >>= 1) v += __shfl_xor_sync(0xffffffffu, v, o);
    return v;
}

/* ------------ 128x128x8 double-buffered fp32 mainloop (round-8 proven) ------- */
__device__ __forceinline__ void gemm_mainloop(
    const float* __restrict__ A, const float* __restrict__ B, int K,
    float (&acc)[8][8], float* sa, float* sb)
{
    int tid = threadIdx.x;
    int tx = tid & 15, ty = tid >> 4;
    int lr = tid >> 1;              /* 0..127 */
    int lk = (tid & 1) * 4;         /* 0 or 4 */
    const float* ap = A + (size_t)lr * K + lk;
    const float* bp = B + (size_t)lr * K + lk;

    /* preload chunk 0 */
    {
        float4 av = *(const float4*)ap;
        float4 bv = *(const float4*)bp;
        sa[(lk + 0) * PAD_LD + lr] = av.x; sa[(lk + 1) * PAD_LD + lr] = av.y;
        sa[(lk + 2) * PAD_LD + lr] = av.z; sa[(lk + 3) * PAD_LD + lr] = av.w;
        sb[(lk + 0) * PAD_LD + lr] = bv.x; sb[(lk + 1) * PAD_LD + lr] = bv.y;
        sb[(lk + 2) * PAD_LD + lr] = bv.z; sb[(lk + 3) * PAD_LD + lr] = bv.w;
    }
    __syncthreads();

    int buf = 0;
    int nch = K / KC;
    for (int ch = 0; ch < nch; ch++) {
        float4 anx, bnx;
        bool more = (ch + 1 < nch);
        if (more) {
            anx = *(const float4*)(ap + (ch + 1) * KC);
            bnx = *(const float4*)(bp + (ch + 1) * KC);
        }
        const float* ca = sa + buf * SBUF;
        const float* cb = sb + buf * SBUF;
#pragma unroll
        for (int k = 0; k < KC; k++) {
            float4 a0 = *(const float4*)(ca + k * PAD_LD + ty * 4);
            float4 a1 = *(const float4*)(ca + k * PAD_LD + 64 + ty * 4);
            float4 b0 = *(const float4*)(cb + k * PAD_LD + tx * 4);
            float4 b1 = *(const float4*)(cb + k * PAD_LD + 64 + tx * 4);
            float ar[8] = {a0.x, a0.y, a0.z, a0.w, a1.x, a1.y, a1.z, a1.w};
            float br[8] = {b0.x, b0.y, b0.z, b0.w, b1.x, b1.y, b1.z, b1.w};
#pragma unroll
            for (int i = 0; i < 8; i++)
#pragma unroll
                for (int j = 0; j < 8; j++)
                    acc[i][j] = fmaf(ar[i], br[j], acc[i][j]);
        }
        if (more) {
            int nb = buf ^ 1;
            float* na = sa + nb * SBUF;
            float* nbf = sb + nb * SBUF;
            na[(lk + 0) * PAD_LD + lr] = anx.x; na[(lk + 1) * PAD_LD + lr] = anx.y;
            na[(lk + 2) * PAD_LD + lr] = anx.z; na[(lk + 3) * PAD_LD + lr] = anx.w;
            nbf[(lk + 0) * PAD_LD + lr] = bnx.x; nbf[(lk + 1) * PAD_LD + lr] = bnx.y;
            nbf[(lk + 2) * PAD_LD + lr] = bnx.z; nbf[(lk + 3) * PAD_LD + lr] = bnx.w;
            __syncthreads();
            buf = nb;
        }
    }
}

__device__ __forceinline__ int frag_r(int ty, int i) {
    return (i < 4) ? (ty * 4 + i) : (64 + ty * 4 + i - 4);
}

/* ------------ C = alpha*A.B^T + bias (out projection) ------------------------ */
__global__ __launch_bounds__(256) void gemm_abt(
    const float* __restrict__ A, const float* __restrict__ B,
    float* __restrict__ C, const float* __restrict__ bias,
    int N, int K, float alpha,
    size_t sA, size_t sB, size_t sC)
{
    A += (size_t)blockIdx.z * sA;
    B += (size_t)blockIdx.z * sB;
    C += (size_t)blockIdx.z * sC;

    __shared__ float sa[2 * SBUF];
    __shared__ float sb[2 * SBUF];

    int tid = threadIdx.x;
    int tx = tid & 15, ty = tid >> 4;
    int row0 = blockIdx.y * BM, col0 = blockIdx.x * BN;

    float acc[8][8] = {};
    gemm_mainloop(A + (size_t)row0 * K, B + (size_t)col0 * K, K, acc, sa, sb);

    float bl[8] = {};
    if (bias) {
        float4 bb0 = *(const float4*)(bias + col0 + tx * 4);
        float4 bb1 = *(const float4*)(bias + col0 + 64 + tx * 4);
        bl[0] = bb0.x; bl[1] = bb0.y; bl[2] = bb0.z; bl[3] = bb0.w;
        bl[4] = bb1.x; bl[5] = bb1.y; bl[6] = bb1.z; bl[7] = bb1.w;
    }

#pragma unroll
    for (int i = 0; i < 8; i++) {
        int r = row0 + frag_r(ty, i);
        float4 o0, o1;
        o0.x = fmaf(alpha, acc[i][0], bl[0]);
        o0.y = fmaf(alpha, acc[i][1], bl[1]);
        o0.z = fmaf(alpha, acc[i][2], bl[2]);
        o0.w = fmaf(alpha, acc[i][3], bl[3]);
        o1.x = fmaf(alpha, acc[i][4], bl[4]);
        o1.y = fmaf(alpha, acc[i][5], bl[5]);
        o1.z = fmaf(alpha, acc[i][6], bl[6]);
        o1.w = fmaf(alpha, acc[i][7], bl[7]);
        *(float4*)(C + (size_t)r * N + col0 + tx * 4) = o0;
        *(float4*)(C + (size_t)r * N + col0 + 64 + tx * 4) = o1;
    }
}

/* ------------ scores upper triangle: 136 tiles/batch, direct store only ------ */
__global__ __launch_bounds__(256) void scores_sym_kernel(
    const float* __restrict__ x, float* __restrict__ C)
{
    __shared__ float sa[2 * SBUF];
    __shared__ float sb[2 * SBUF];

    /* decode triangular tile (i,j), 0<=i<=j<16 */
    int t = blockIdx.x;
    int i = 0, rem = SEQ / BM;
    while (t >= rem) { t -= rem; rem--; i++; }
    int j = i + t;

    const float* xb = x + (size_t)blockIdx.z * SEQ * EMB;
    float* Cb = C + (size_t)blockIdx.z * SEQ * SEQ;
    int row0 = i * BM, col0 = j * BN;

    float acc[8][8] = {};
    gemm_mainloop(xb + (size_t)row0 * EMB, xb + (size_t)col0 * EMB, EMB, acc, sa, sb);

    int tx = threadIdx.x & 15, ty = threadIdx.x >> 4;
#pragma unroll
    for (int ii = 0; ii < 8; ii++) {
        int r = row0 + frag_r(ty, ii);
        float4 o0 = {acc[ii][0] * 0.0625f, acc[ii][1] * 0.0625f,
                     acc[ii][2] * 0.0625f, acc[ii][3] * 0.0625f};
        float4 o1 = {acc[ii][4] * 0.0625f, acc[ii][5] * 0.0625f,
                     acc[ii][6] * 0.0625f, acc[ii][7] * 0.0625f};
        *(float4*)(Cb + (size_t)r * SEQ + col0 + tx * 4) = o0;
        *(float4*)(Cb + (size_t)r * SEQ + col0 + 64 + tx * 4) = o1;
    }
}

/* ------------ mirror lower triangle via smem transpose (coalesced both ways) - */
__global__ __launch_bounds__(256) void mirror_kernel(float* __restrict__ C)
{
    __shared__ float ts[64 * 65];

    int p = blockIdx.x >> 2, sub = blockIdx.x & 3;
    int I = 1;
    while (p >= I) { p -= I; I++; }
    int J = p;                          /* J < I */

    float* Cb = C + (size_t)blockIdx.z * SEQ * SEQ;
    int dr = I * BM + (sub >> 1) * 64;  /* dest 64-tile origin (lower tri) */
    int dc = J * BM + (sub & 1) * 64;

    int tx = threadIdx.x & 15, ty = threadIdx.x >> 4;

#pragma unroll
    for (int q = 0; q < 4; q++) {
        int r = ty + q * 16;
        float4 s = *(const float4*)(Cb + (size_t)(dc + r) * SEQ + dr + tx * 4);
        ts[(tx * 4 + 0) * 65 + r] = s.x;
        ts[(tx * 4 + 1) * 65 + r] = s.y;
        ts[(tx * 4 + 2) * 65 + r] = s.z;
        ts[(tx * 4 + 3) * 65 + r] = s.w;
    }
    __syncthreads();

#pragma unroll
    for (int q = 0; q < 4; q++) {
        int j = ty + q * 16;
        float4 o;
        o.x = ts[j * 65 + tx * 4 + 0];
        o.y = ts[j * 65 + tx * 4 + 1];
        o.z = ts[j * 65 + tx * 4 + 2];
        o.w = ts[j * 65 + tx * 4 + 3];
        *(float4*)(Cb + (size_t)(dr + j) * SEQ + dc + tx * 4) = o;
    }
}

/* ------------ fused QKV projection: blockIdx.x = seg*2 + colblk, 384 CTAs ---- */
__global__ __launch_bounds__(256) void qkv_kernel(
    const float* __restrict__ x,
    const float* __restrict__ Wq, const float* __restrict__ Wk, const float* __restrict__ Wv,
    const float* __restrict__ bq, const float* __restrict__ bk, const float* __restrict__ bv,
    float* __restrict__ q, float* __restrict__ k, float* __restrict__ v)
{
    __shared__ float sa[2 * SBUF];
    __shared__ float sb[2 * SBUF];

    int seg = blockIdx.x >> 1;
    const float* W    = (seg == 0) ? Wq : (seg == 1) ? Wk : Wv;
    const float* bias = (seg == 0) ? bq : (seg == 1) ? bk : bv;
    float*       out  = (seg == 0) ? q  : (seg == 1) ? k  : v;
    int col0 = (blockIdx.x & 1) * BN;
    int row0 = blockIdx.y * BM;

    float acc[8][8] = {};
    gemm_mainloop(x + (size_t)row0 * EMB, W + (size_t)col0 * EMB, EMB, acc, sa, sb);

    int tx = threadIdx.x & 15, ty = threadIdx.x >> 4;
    float4 bb0 = *(const float4*)(bias + col0 + tx * 4);
    float4 bb1 = *(const float4*)(bias + col0 + 64 + tx * 4);
    float bl[8] = {bb0.x, bb0.y, bb0.z, bb0.w, bb1.x, bb1.y, bb1.z, bb1.w};

#pragma unroll
    for (int ii = 0; ii < 8; ii++) {
        int r = row0 + frag_r(ty, ii);
        float4 o0 = {acc[ii][0] + bl[0], acc[ii][1] + bl[1], acc[ii][2] + bl[2], acc[ii][3] + bl[3]};
        float4 o1 = {acc[ii][4] + bl[4], acc[ii][5] + bl[5], acc[ii][6] + bl[6], acc[ii][7] + bl[7]};
        *(float4*)(out + (size_t)r * EMB + col0 + tx * 4) = o0;
        *(float4*)(out + (size_t)r * EMB + col0 + 64 + tx * 4) = o1;
    }
}

/* ------------ exact per-row top-k v2: register keys, warp-aggregated hist ---- */
__global__ __launch_bounds__(256) void topk_kernel(
    const float* __restrict__ scores, int* __restrict__ idx)
{
    int row = blockIdx.x;                 /* 0..8191 */
    int tid = threadIdx.x;
    int lane = tid & 31;
    __shared__ unsigned int hist[256];
    __shared__ unsigned int bc[2];
    __shared__ unsigned int thcnt[256];
    __shared__ unsigned int cnt;

    const float* srow = scores + (size_t)row * SEQ;
    int base = tid * 8;
    unsigned int key[8];
    {
        float4 f0 = *(const float4*)(srow + base);
        float4 f1 = *(const float4*)(srow + base + 4);
        float fv[8] = {f0.x, f0.y, f0.z, f0.w, f1.x, f1.y, f1.z, f1.w};
#pragma unroll
        for (int e = 0; e < 8; e++) {
            unsigned int b = __float_as_uint(fv[e]);
            key[e] = b ^ ((b & 0x80000000u) ? 0xFFFFFFFFu : 0x80000000u);
        }
    }
    if (tid == 0) cnt = 0;

    unsigned int remaining = KSEL;
    unsigned int prefix = 0;

#pragma unroll
    for (int shift = 24; shift >= 0; shift -= 8) {
        unsigned int himask = (shift == 24) ? 0u : (0xFFFFFFFFu << (shift + 8));
        hist[tid] = 0;
        __syncthreads();
        /* histogram with warp-aggregated atomics (hot exponent bins) */
#pragma unroll
        for (int e = 0; e < 8; e++) {
            bool valid = (key[e] & himask) == prefix;
            unsigned int bin = (key[e] >> shift) & 255u;
            unsigned int mk = __match_any_sync(0xffffffffu, valid ? bin : 0x400u);
            if (valid) {
                if (lane == __ffs(mk) - 1)
                    atomicAdd(&hist[bin], (unsigned int)__popc(mk));
            }
        }
        __syncthreads();
        /* warp-0 suffix-scan bucket select: lane owns bins [lane*8, lane*8+8) */
        if (tid < 32) {
            unsigned int h[8];
            unsigned int t = 0;
#pragma unroll
            for (int j2 = 0; j2 < 8; j2++) { h[j2] = hist[tid * 8 + j2]; t += h[j2]; }
            unsigned int s = t;                    /* inclusive cross-lane suffix */
#pragma unroll
            for (int o = 1; o < 32; o <<= 1) {
                unsigned int vv = __shfl_down_sync(0xffffffffu, s, o);
                if (lane + o < 32) s += vv;
            }
            unsigned int run = s - t;              /* S[(lane+1)*8] */
#pragma unroll
            for (int j2 = 7; j2 >= 0; j2--) {
                unsigned int Sb = run + h[j2];     /* S[bin], run = S[bin+1] */
                if (Sb >= remaining && run < remaining) {
                    bc[0] = prefix | ((unsigned int)(tid * 8 + j2) << shift);
                    bc[1] = remaining - run;
                }
                run = Sb;
            }
        }
        __syncthreads();
        prefix = bc[0];
        remaining = bc[1];
        __syncthreads();
    }

    unsigned int T = prefix;                    /* exact k-th largest key */
    unsigned int ties_allowed = remaining;
    unsigned int gbase = KSEL - remaining;

    /* strictly greater: ballot-compacted, one atomic per warp per slot */
#pragma unroll
    for (int e = 0; e < 8; e++) {
        unsigned int bal = __ballot_sync(0xffffffffu, key[e] > T);
        if (bal) {
            int leader = __ffs(bal) - 1;
            unsigned int slotbase = 0;
            if (lane == leader)
                slotbase = atomicAdd(&cnt, (unsigned int)__popc(bal));
            slotbase = __shfl_sync(0xffffffffu, slotbase, leader);
            if (key[e] > T) {
                unsigned int rank = __popc(bal & ((1u << lane) - 1u));
                idx[(size_t)row * KSEL + slotbase + rank] = base + e;
            }
        }
    }

    /* ties: blocked ownership -> ascending index order (proven scan) */
    unsigned int local = 0;
#pragma unroll
    for (int i = 0; i < 8; i++) if (key[i] == T) local++;
    thcnt[tid] = local;
    for (int off = 1; off < 256; off <<= 1) {
        __syncthreads();
        unsigned int vv = (tid >= off) ? thcnt[tid - off] : 0u;
        __syncthreads();
        thcnt[tid] += vv;
    }
    __syncthreads();
    unsigned int r = thcnt[tid] - local;
#pragma unroll
    for (int i = 0; i < 8; i++) {
        if (key[i] == T) {
            if (r < ties_allowed)
                idx[(size_t)row * KSEL + gbase + r] = base + i;
            r++;
        }
    }
}

/* ------------ fused sparse attention v5: phase-1 unrolled x2 (MLP 2->4) ------ */
__global__ __launch_bounds__(256) void sparse_attn_kernel(
    const float* __restrict__ q, const float* __restrict__ k,
    const float* __restrict__ v, const int* __restrict__ idx,
    float* __restrict__ ctx, float* __restrict__ attn_out)
{
    int row = blockIdx.x;          /* b*SEQ + s */
    int b = row >> 11;
    int tid = threadIdx.x;
    int warp = tid >> 5, lane = tid & 31;

    __shared__ alignas(16) float qs[EMB];
    __shared__ alignas(16) int   sidx[KSEL_PAD];
    __shared__ alignas(16) float lg[HEADS][KSEL_PAD];
    __shared__ alignas(16) float rowbuf[SEQ];

    qs[tid] = q[(size_t)row * EMB + tid];
    if (tid < KSEL) sidx[tid] = idx[(size_t)row * KSEL + tid];
    __syncthreads();

    float4 q0 = *(const float4*)&qs[lane * 4];
    float4 q1 = *(const float4*)&qs[128 + lane * 4];

    const float* kb = k + (size_t)b * SEQ * EMB;
    int h_lo = lane >> 3;
    int h_hi = 4 + (lane >> 3);
    /* two columns per iteration: all 4 LDG.128s issued before the SHFL chains */
    for (int j = warp; j < KSEL; j += 16) {
        int jb = j + 8;
        bool has2 = (jb < KSEL);
        const float* kra = kb + (size_t)sidx[j] * EMB;
        const float* krb = has2 ? (kb + (size_t)sidx[jb] * EMB) : kra;
        float4 a0 = *(const float4*)(kra + lane * 4);
        float4 a1 = *(const float4*)(kra + 128 + lane * 4);
        float4 b0 = *(const float4*)(krb + lane * 4);
        float4 b1 = *(const float4*)(krb + 128 + lane * 4);

        float sa0 = a0.x * q0.x + a0.y * q0.y + a0.z * q0.z + a0.w * q0.w;
        float sa1 = a1.x * q1.x + a1.y * q1.y + a1.z * q1.z + a1.w * q1.w;
        float sb0 = b0.x * q0.x + b0.y * q0.y + b0.z * q0.z + b0.w * q0.w;
        float sb1 = b1.x * q1.x + b1.y * q1.y + b1.z * q1.z + b1.w * q1.w;
#pragma unroll
        for (int o = 1; o < 8; o <<= 1) {
            sa0 += __shfl_xor_sync(0xffffffffu, sa0, o);
            sa1 += __shfl_xor_sync(0xffffffffu, sa1, o);
            sb0 += __shfl_xor_sync(0xffffffffu, sb0, o);
            sb1 += __shfl_xor_sync(0xffffffffu, sb1, o);
        }
        if ((lane & 7) == 0) {
            lg[h_lo][j] = sa0 * 0.17677669529663687f;
            lg[h_hi][j] = sa1 * 0.17677669529663687f;
            if (has2) {
                lg[h_lo][jb] = sb0 * 0.17677669529663687f;
                lg[h_hi][jb] = sb1 * 0.17677669529663687f;
            }
        }
    }
    __syncthreads();

    {
        int h = warp;
        float m = -1e30f;
        for (int j = lane; j < KSEL; j += 32) m = fmaxf(m, lg[h][j]);
#pragma unroll
        for (int o = 16; o; o >>= 1) m = fmaxf(m, __shfl_xor_sync(0xffffffffu, m, o));
        float s = 0.f;
        for (int j = lane; j < KSEL; j += 32) {
            float e = fexp(lg[h][j] - m);
            lg[h][j] = e;
            s += e;
        }
        s = warp_sum(s);
        float inv = 1.f / s;
        for (int j = lane; j < KSEL; j += 32) lg[h][j] *= inv;
    }
    __syncthreads();

    {
        int hh = warp;
        const float* vb = v + (size_t)b * SEQ * EMB + tid;
        const float4* lg4 = (const float4*)&lg[hh][0];
        const int4*   sx4 = (const int4*)sidx;
        float a0 = 0.f, a1 = 0.f, a2 = 0.f, a3 = 0.f;
#pragma unroll 4
        for (int j4 = 0; j4 < KSEL / 4; j4++) {
            float4 p = lg4[j4];
            int4   t = sx4[j4];
            a0 = fmaf(p.x, vb[(size_t)t.x * EMB], a0);
            a1 = fmaf(p.y, vb[(size_t)t.y * EMB], a1);
            a2 = fmaf(p.z, vb[(size_t)t.z * EMB], a2);
            a3 = fmaf(p.w, vb[(size_t)t.w * EMB], a3);
        }
        ctx[(size_t)row * EMB + tid] = (a0 + a1) + (a2 + a3);
    }

    for (int t0 = tid; t0 < SEQ; t0 += 256) rowbuf[t0] = 0.f;
    __syncthreads();
    if (tid < KSEL) {
        float pm = 0.f;
#pragma unroll
        for (int hh = 0; hh < HEADS; hh++) pm += lg[hh][tid];
        rowbuf[sidx[tid]] = pm * 0.125f;
    }
    __syncthreads();
    float4* dst = (float4*)(attn_out + (size_t)row * SEQ);
    const float4* src = (const float4*)rowbuf;
    for (int t0 = tid; t0 < SEQ / 4; t0 += 256) dst[t0] = src[t0];
}

/* ------------ launch (round-13 proven structure) ------------ */
extern "C" void kernel_launch(void* const* d_in, const int* in_sizes, int n_in,
                              void* d_out, int out_size)
{
    const float* x  = (const float*)d_in[0];
    const float* Wq = (const float*)d_in[1];
    const float* bq = (const float*)d_in[2];
    const float* Wk = (const float*)d_in[3];
    const float* bk = (const float*)d_in[4];
    const float* Wv = (const float*)d_in[5];
    const float* bv = (const float*)d_in[6];
    const float* Wo = (const float*)d_in[7];
    const float* bo = (const float*)d_in[8];

    float* out  = (float*)d_out;
    float* attn = out + (size_t)BATCH * SEQ * EMB;

    float *scores, *q, *k, *v, *ctx;
    int* idx;
    cudaGetSymbolAddress((void**)&scores, g_scores);
    cudaGetSymbolAddress((void**)&idx,    g_idx);
    cudaGetSymbolAddress((void**)&q,      g_q);
    cudaGetSymbolAddress((void**)&k,      g_k);
    cudaGetSymbolAddress((void**)&v,      g_v);
    cudaGetSymbolAddress((void**)&ctx,    g_ctx);

    /* 1a. scores upper triangle = x @ x^T / 16 (136 tiles/batch) */
    scores_sym_kernel<<<dim3(136, 1, BATCH), 256>>>(x, scores);
    /* 1b. mirror lower triangle via coalesced smem transpose */
    mirror_kernel<<<dim3(480, 1, BATCH), 256>>>(scores);

    /* 2. exact top-k index selection per row */
    topk_kernel<<<BATCH * SEQ, 256>>>(scores, idx);

    /* 3. fused q/k/v projections: one launch, 384 CTAs */
    qkv_kernel<<<dim3(6, (BATCH * SEQ) / BM), 256>>>(
        x, Wq, Wk, Wv, bq, bk, bv, q, k, v);

    /* 4. fused sparse attention + attn_weights output */
    sparse_attn_kernel<<<BATCH * SEQ, 256>>>(q, k, v, idx, ctx, attn);

    /* 5. out = ctx @ Wo^T + bo */
    gemm_abt<<<dim3(EMB / BN, (BATCH * SEQ) / BM, 1), 256>>>(
        ctx, Wo, out, bo, EMB, EMB, 1.0f, 0, 0, 0);
}

// round 17
// speedup vs baseline: 1.6215x; 1.0008x over previous
#include <cuda_runtime.h>
#include <math.h>

#define BATCH 4
#define SEQ   2048
#define EMB   256
#define HEADS 8
#define HDIM  32
#define KSEL  204        /* int(2048*0.1) */
#define KSEL_PAD 208

#define KC 8
#define BM 128
#define BN 128
#define PAD_LD 132       /* 132 floats = 528B, 16B-aligned rows, conflict-free */
#define SBUF (KC * PAD_LD)

/* ------------ scratch (no allocations allowed) ------------ */
__device__ float g_scores[(size_t)BATCH * SEQ * SEQ];   /* 67 MB */
__device__ int   g_idx[BATCH * SEQ * KSEL];
__device__ float g_q[(size_t)BATCH * SEQ * EMB];
__device__ float g_k[(size_t)BATCH * SEQ * EMB];
__device__ float g_v[(size_t)BATCH * SEQ * EMB];
__device__ float g_ctx[(size_t)BATCH * SEQ * EMB];

/* ------------ fast exp on the FMA pipe (avoids MUFU) ------------ */
__device__ __forceinline__ float fexp(float x) {
    float y = x * 1.4426950408889634f;
    if (y < -126.0f) return 0.0f;
    float n = floorf(y);
    float f = y - n;
    float p = 1.33988744e-3f;
    p = fmaf(p, f, 9.61843735e-3f);
    p = fmaf(p, f, 5.55033250e-2f);
    p = fmaf(p, f, 2.40226448e-1f);
    p = fmaf(p, f, 6.93147202e-1f);
    p = fmaf(p, f, 1.0f);
    return p * __int_as_float(((int)n + 127) << 23);
}

/* full-warp fp32 sum via butterfly shuffles (no fp32 REDUX on sm_103) */
__device__ __forceinline__ float warp_sum(float v) {
#pragma unroll
    for (int o = 16; o; o >>= 1) v += __shfl_xor_sync(0xffffffffu, v, o);
    return v;
}

/* ------------ 128x128x8 double-buffered fp32 mainloop (round-8 proven) ------- */
__device__ __forceinline__ void gemm_mainloop(
    const float* __restrict__ A, const float* __restrict__ B, int K,
    float (&acc)[8][8], float* sa, float* sb)
{
    int tid = threadIdx.x;
    int tx = tid & 15, ty = tid >> 4;
    int lr = tid >> 1;              /* 0..127 */
    int lk = (tid & 1) * 4;         /* 0 or 4 */
    const float* ap = A + (size_t)lr * K + lk;
    const float* bp = B + (size_t)lr * K + lk;

    /* preload chunk 0 */
    {
        float4 av = *(const float4*)ap;
        float4 bv = *(const float4*)bp;
        sa[(lk + 0) * PAD_LD + lr] = av.x; sa[(lk + 1) * PAD_LD + lr] = av.y;
        sa[(lk + 2) * PAD_LD + lr] = av.z; sa[(lk + 3) * PAD_LD + lr] = av.w;
        sb[(lk + 0) * PAD_LD + lr] = bv.x; sb[(lk + 1) * PAD_LD + lr] = bv.y;
        sb[(lk + 2) * PAD_LD + lr] = bv.z; sb[(lk + 3) * PAD_LD + lr] = bv.w;
    }
    __syncthreads();

    int buf = 0;
    int nch = K / KC;
    for (int ch = 0; ch < nch; ch++) {
        float4 anx, bnx;
        bool more = (ch + 1 < nch);
        if (more) {
            anx = *(const float4*)(ap + (ch + 1) * KC);
            bnx = *(const float4*)(bp + (ch + 1) * KC);
        }
        const float* ca = sa + buf * SBUF;
        const float* cb = sb + buf * SBUF;
#pragma unroll
        for (int k = 0; k < KC; k++) {
            float4 a0 = *(const float4*)(ca + k * PAD_LD + ty * 4);
            float4 a1 = *(const float4*)(ca + k * PAD_LD + 64 + ty * 4);
            float4 b0 = *(const float4*)(cb + k * PAD_LD + tx * 4);
            float4 b1 = *(const float4*)(cb + k * PAD_LD + 64 + tx * 4);
            float ar[8] = {a0.x, a0.y, a0.z, a0.w, a1.x, a1.y, a1.z, a1.w};
            float br[8] = {b0.x, b0.y, b0.z, b0.w, b1.x, b1.y, b1.z, b1.w};
#pragma unroll
            for (int i = 0; i < 8; i++)
#pragma unroll
                for (int j = 0; j < 8; j++)
                    acc[i][j] = fmaf(ar[i], br[j], acc[i][j]);
        }
        if (more) {
            int nb = buf ^ 1;
            float* na = sa + nb * SBUF;
            float* nbf = sb + nb * SBUF;
            na[(lk + 0) * PAD_LD + lr] = anx.x; na[(lk + 1) * PAD_LD + lr] = anx.y;
            na[(lk + 2) * PAD_LD + lr] = anx.z; na[(lk + 3) * PAD_LD + lr] = anx.w;
            nbf[(lk + 0) * PAD_LD + lr] = bnx.x; nbf[(lk + 1) * PAD_LD + lr] = bnx.y;
            nbf[(lk + 2) * PAD_LD + lr] = bnx.z; nbf[(lk + 3) * PAD_LD + lr] = bnx.w;
            __syncthreads();
            buf = nb;
        }
    }
}

__device__ __forceinline__ int frag_r(int ty, int i) {
    return (i < 4) ? (ty * 4 + i) : (64 + ty * 4 + i - 4);
}

/* ------------ C = alpha*A.B^T + bias (out projection) ------------------------ */
__global__ __launch_bounds__(256) void gemm_abt(
    const float* __restrict__ A, const float* __restrict__ B,
    float* __restrict__ C, const float* __restrict__ bias,
    int N, int K, float alpha,
    size_t sA, size_t sB, size_t sC)
{
    A += (size_t)blockIdx.z * sA;
    B += (size_t)blockIdx.z * sB;
    C += (size_t)blockIdx.z * sC;

    __shared__ float sa[2 * SBUF];
    __shared__ float sb[2 * SBUF];

    int tid = threadIdx.x;
    int tx = tid & 15, ty = tid >> 4;
    int row0 = blockIdx.y * BM, col0 = blockIdx.x * BN;

    float acc[8][8] = {};
    gemm_mainloop(A + (size_t)row0 * K, B + (size_t)col0 * K, K, acc, sa, sb);

    float bl[8] = {};
    if (bias) {
        float4 bb0 = *(const float4*)(bias + col0 + tx * 4);
        float4 bb1 = *(const float4*)(bias + col0 + 64 + tx * 4);
        bl[0] = bb0.x; bl[1] = bb0.y; bl[2] = bb0.z; bl[3] = bb0.w;
        bl[4] = bb1.x; bl[5] = bb1.y; bl[6] = bb1.z; bl[7] = bb1.w;
    }

#pragma unroll
    for (int i = 0; i < 8; i++) {
        int r = row0 + frag_r(ty, i);
        float4 o0, o1;
        o0.x = fmaf(alpha, acc[i][0], bl[0]);
        o0.y = fmaf(alpha, acc[i][1], bl[1]);
        o0.z = fmaf(alpha, acc[i][2], bl[2]);
        o0.w = fmaf(alpha, acc[i][3], bl[3]);
        o1.x = fmaf(alpha, acc[i][4], bl[4]);
        o1.y = fmaf(alpha, acc[i][5], bl[5]);
        o1.z = fmaf(alpha, acc[i][6], bl[6]);
        o1.w = fmaf(alpha, acc[i][7], bl[7]);
        *(float4*)(C + (size_t)r * N + col0 + tx * 4) = o0;
        *(float4*)(C + (size_t)r * N + col0 + 64 + tx * 4) = o1;
    }
}

/* ------------ scores upper triangle: 136 tiles/batch, direct store only ------ */
__global__ __launch_bounds__(256) void scores_sym_kernel(
    const float* __restrict__ x, float* __restrict__ C)
{
    __shared__ float sa[2 * SBUF];
    __shared__ float sb[2 * SBUF];

    /* decode triangular tile (i,j), 0<=i<=j<16 */
    int t = blockIdx.x;
    int i = 0, rem = SEQ / BM;
    while (t >= rem) { t -= rem; rem--; i++; }
    int j = i + t;

    const float* xb = x + (size_t)blockIdx.z * SEQ * EMB;
    float* Cb = C + (size_t)blockIdx.z * SEQ * SEQ;
    int row0 = i * BM, col0 = j * BN;

    float acc[8][8] = {};
    gemm_mainloop(xb + (size_t)row0 * EMB, xb + (size_t)col0 * EMB, EMB, acc, sa, sb);

    int tx = threadIdx.x & 15, ty = threadIdx.x >> 4;
#pragma unroll
    for (int ii = 0; ii < 8; ii++) {
        int r = row0 + frag_r(ty, ii);
        float4 o0 = {acc[ii][0] * 0.0625f, acc[ii][1] * 0.0625f,
                     acc[ii][2] * 0.0625f, acc[ii][3] * 0.0625f};
        float4 o1 = {acc[ii][4] * 0.0625f, acc[ii][5] * 0.0625f,
                     acc[ii][6] * 0.0625f, acc[ii][7] * 0.0625f};
        *(float4*)(Cb + (size_t)r * SEQ + col0 + tx * 4) = o0;
        *(float4*)(Cb + (size_t)r * SEQ + col0 + 64 + tx * 4) = o1;
    }
}

/* ------------ mirror lower triangle via smem transpose (coalesced both ways) - */
__global__ __launch_bounds__(256) void mirror_kernel(float* __restrict__ C)
{
    __shared__ float ts[64 * 65];

    int p = blockIdx.x >> 2, sub = blockIdx.x & 3;
    int I = 1;
    while (p >= I) { p -= I; I++; }
    int J = p;                          /* J < I */

    float* Cb = C + (size_t)blockIdx.z * SEQ * SEQ;
    int dr = I * BM + (sub >> 1) * 64;  /* dest 64-tile origin (lower tri) */
    int dc = J * BM + (sub & 1) * 64;

    int tx = threadIdx.x & 15, ty = threadIdx.x >> 4;

#pragma unroll
    for (int q = 0; q < 4; q++) {
        int r = ty + q * 16;
        float4 s = *(const float4*)(Cb + (size_t)(dc + r) * SEQ + dr + tx * 4);
        ts[(tx * 4 + 0) * 65 + r] = s.x;
        ts[(tx * 4 + 1) * 65 + r] = s.y;
        ts[(tx * 4 + 2) * 65 + r] = s.z;
        ts[(tx * 4 + 3) * 65 + r] = s.w;
    }
    __syncthreads();

#pragma unroll
    for (int q = 0; q < 4; q++) {
        int j = ty + q * 16;
        float4 o;
        o.x = ts[j * 65 + tx * 4 + 0];
        o.y = ts[j * 65 + tx * 4 + 1];
        o.z = ts[j * 65 + tx * 4 + 2];
        o.w = ts[j * 65 + tx * 4 + 3];
        *(float4*)(Cb + (size_t)(dr + j) * SEQ + dc + tx * 4) = o;
    }
}

/* ------------ fused QKV projection: blockIdx.x = seg*2 + colblk, 384 CTAs ---- */
__global__ __launch_bounds__(256) void qkv_kernel(
    const float* __restrict__ x,
    const float* __restrict__ Wq, const float* __restrict__ Wk, const float* __restrict__ Wv,
    const float* __restrict__ bq, const float* __restrict__ bk, const float* __restrict__ bv,
    float* __restrict__ q, float* __restrict__ k, float* __restrict__ v)
{
    __shared__ float sa[2 * SBUF];
    __shared__ float sb[2 * SBUF];

    int seg = blockIdx.x >> 1;
    const float* W    = (seg == 0) ? Wq : (seg == 1) ? Wk : Wv;
    const float* bias = (seg == 0) ? bq : (seg == 1) ? bk : bv;
    float*       out  = (seg == 0) ? q  : (seg == 1) ? k  : v;
    int col0 = (blockIdx.x & 1) * BN;
    int row0 = blockIdx.y * BM;

    float acc[8][8] = {};
    gemm_mainloop(x + (size_t)row0 * EMB, W + (size_t)col0 * EMB, EMB, acc, sa, sb);

    int tx = threadIdx.x & 15, ty = threadIdx.x >> 4;
    float4 bb0 = *(const float4*)(bias + col0 + tx * 4);
    float4 bb1 = *(const float4*)(bias + col0 + 64 + tx * 4);
    float bl[8] = {bb0.x, bb0.y, bb0.z, bb0.w, bb1.x, bb1.y, bb1.z, bb1.w};

#pragma unroll
    for (int ii = 0; ii < 8; ii++) {
        int r = row0 + frag_r(ty, ii);
        float4 o0 = {acc[ii][0] + bl[0], acc[ii][1] + bl[1], acc[ii][2] + bl[2], acc[ii][3] + bl[3]};
        float4 o1 = {acc[ii][4] + bl[4], acc[ii][5] + bl[5], acc[ii][6] + bl[6], acc[ii][7] + bl[7]};
        *(float4*)(out + (size_t)r * EMB + col0 + tx * 4) = o0;
        *(float4*)(out + (size_t)r * EMB + col0 + 64 + tx * 4) = o1;
    }
}

/* ------------ exact per-row top-k v2: register keys, warp-aggregated hist ---- */
__global__ __launch_bounds__(256) void topk_kernel(
    const float* __restrict__ scores, int* __restrict__ idx)
{
    int row = blockIdx.x;                 /* 0..8191 */
    int tid = threadIdx.x;
    int lane = tid & 31;
    __shared__ unsigned int hist[256];
    __shared__ unsigned int bc[2];
    __shared__ unsigned int thcnt[256];
    __shared__ unsigned int cnt;

    const float* srow = scores + (size_t)row * SEQ;
    int base = tid * 8;
    unsigned int key[8];
    {
        float4 f0 = *(const float4*)(srow + base);
        float4 f1 = *(const float4*)(srow + base + 4);
        float fv[8] = {f0.x, f0.y, f0.z, f0.w, f1.x, f1.y, f1.z, f1.w};
#pragma unroll
        for (int e = 0; e < 8; e++) {
            unsigned int b = __float_as_uint(fv[e]);
            key[e] = b ^ ((b & 0x80000000u) ? 0xFFFFFFFFu : 0x80000000u);
        }
    }
    if (tid == 0) cnt = 0;

    unsigned int remaining = KSEL;
    unsigned int prefix = 0;

#pragma unroll
    for (int shift = 24; shift >= 0; shift -= 8) {
        unsigned int himask = (shift == 24) ? 0u : (0xFFFFFFFFu << (shift + 8));
        hist[tid] = 0;
        __syncthreads();
        /* histogram with warp-aggregated atomics (hot exponent bins) */
#pragma unroll
        for (int e = 0; e < 8; e++) {
            bool valid = (key[e] & himask) == prefix;
            unsigned int bin = (key[e] >> shift) & 255u;
            unsigned int mk = __match_any_sync(0xffffffffu, valid ? bin : 0x400u);
            if (valid) {
                if (lane == __ffs(mk) - 1)
                    atomicAdd(&hist[bin], (unsigned int)__popc(mk));
            }
        }
        __syncthreads();
        /* warp-0 suffix-scan bucket select: lane owns bins [lane*8, lane*8+8) */
        if (tid < 32) {
            unsigned int h[8];
            unsigned int t = 0;
#pragma unroll
            for (int j2 = 0; j2 < 8; j2++) { h[j2] = hist[tid * 8 + j2]; t += h[j2]; }
            unsigned int s = t;                    /* inclusive cross-lane suffix */
#pragma unroll
            for (int o = 1; o < 32; o <<= 1) {
                unsigned int vv = __shfl_down_sync(0xffffffffu, s, o);
                if (lane + o < 32) s += vv;
            }
            unsigned int run = s - t;              /* S[(lane+1)*8] */
#pragma unroll
            for (int j2 = 7; j2 >= 0; j2--) {
                unsigned int Sb = run + h[j2];     /* S[bin], run = S[bin+1] */
                if (Sb >= remaining && run < remaining) {
                    bc[0] = prefix | ((unsigned int)(tid * 8 + j2) << shift);
                    bc[1] = remaining - run;
                }
                run = Sb;
            }
        }
        __syncthreads();
        prefix = bc[0];
        remaining = bc[1];
        __syncthreads();
    }

    unsigned int T = prefix;                    /* exact k-th largest key */
    unsigned int ties_allowed = remaining;
    unsigned int gbase = KSEL - remaining;

    /* strictly greater: ballot-compacted, one atomic per warp per slot */
#pragma unroll
    for (int e = 0; e < 8; e++) {
        unsigned int bal = __ballot_sync(0xffffffffu, key[e] > T);
        if (bal) {
            int leader = __ffs(bal) - 1;
            unsigned int slotbase = 0;
            if (lane == leader)
                slotbase = atomicAdd(&cnt, (unsigned int)__popc(bal));
            slotbase = __shfl_sync(0xffffffffu, slotbase, leader);
            if (key[e] > T) {
                unsigned int rank = __popc(bal & ((1u << lane) - 1u));
                idx[(size_t)row * KSEL + slotbase + rank] = base + e;
            }
        }
    }

    /* ties: blocked ownership -> ascending index order (proven scan) */
    unsigned int local = 0;
#pragma unroll
    for (int i = 0; i < 8; i++) if (key[i] == T) local++;
    thcnt[tid] = local;
    for (int off = 1; off < 256; off <<= 1) {
        __syncthreads();
        unsigned int vv = (tid >= off) ? thcnt[tid - off] : 0u;
        __syncthreads();
        thcnt[tid] += vv;
    }
    __syncthreads();
    unsigned int r = thcnt[tid] - local;
#pragma unroll
    for (int i = 0; i < 8; i++) {
        if (key[i] == T) {
            if (r < ties_allowed)
                idx[(size_t)row * KSEL + gbase + r] = base + i;
            r++;
        }
    }
}

/* ------------ fused sparse attention v5: phase-1 unrolled x2 (round-16) ------ */
__global__ __launch_bounds__(256) void sparse_attn_kernel(
    const float* __restrict__ q, const float* __restrict__ k,
    const float* __restrict__ v, const int* __restrict__ idx,
    float* __restrict__ ctx, float* __restrict__ attn_out)
{
    int row = blockIdx.x;          /* b*SEQ + s */
    int b = row >> 11;
    int tid = threadIdx.x;
    int warp = tid >> 5, lane = tid & 31;

    __shared__ alignas(16) float qs[EMB];
    __shared__ alignas(16) int   sidx[KSEL_PAD];
    __shared__ alignas(16) float lg[HEADS][KSEL_PAD];
    __shared__ alignas(16) float rowbuf[SEQ];

    qs[tid] = q[(size_t)row * EMB + tid];
    if (tid < KSEL) sidx[tid] = idx[(size_t)row * KSEL + tid];
    __syncthreads();

    float4 q0 = *(const float4*)&qs[lane * 4];
    float4 q1 = *(const float4*)&qs[128 + lane * 4];

    const float* kb = k + (size_t)b * SEQ * EMB;
    int h_lo = lane >> 3;
    int h_hi = 4 + (lane >> 3);
    /* two columns per iteration: all 4 LDG.128s issued before the SHFL chains */
    for (int j = warp; j < KSEL; j += 16) {
        int jb = j + 8;
        bool has2 = (jb < KSEL);
        const float* kra = kb + (size_t)sidx[j] * EMB;
        const float* krb = has2 ? (kb + (size_t)sidx[jb] * EMB) : kra;
        float4 a0 = *(const float4*)(kra + lane * 4);
        float4 a1 = *(const float4*)(kra + 128 + lane * 4);
        float4 b0 = *(const float4*)(krb + lane * 4);
        float4 b1 = *(const float4*)(krb + 128 + lane * 4);

        float sa0 = a0.x * q0.x + a0.y * q0.y + a0.z * q0.z + a0.w * q0.w;
        float sa1 = a1.x * q1.x + a1.y * q1.y + a1.z * q1.z + a1.w * q1.w;
        float sb0 = b0.x * q0.x + b0.y * q0.y + b0.z * q0.z + b0.w * q0.w;
        float sb1 = b1.x * q1.x + b1.y * q1.y + b1.z * q1.z + b1.w * q1.w;
#pragma unroll
        for (int o = 1; o < 8; o <<= 1) {
            sa0 += __shfl_xor_sync(0xffffffffu, sa0, o);
            sa1 += __shfl_xor_sync(0xffffffffu, sa1, o);
            sb0 += __shfl_xor_sync(0xffffffffu, sb0, o);
            sb1 += __shfl_xor_sync(0xffffffffu, sb1, o);
        }
        if ((lane & 7) == 0) {
            lg[h_lo][j] = sa0 * 0.17677669529663687f;
            lg[h_hi][j] = sa1 * 0.17677669529663687f;
            if (has2) {
                lg[h_lo][jb] = sb0 * 0.17677669529663687f;
                lg[h_hi][jb] = sb1 * 0.17677669529663687f;
            }
        }
    }
    __syncthreads();

    {
        int h = warp;
        float m = -1e30f;
        for (int j = lane; j < KSEL; j += 32) m = fmaxf(m, lg[h][j]);
#pragma unroll
        for (int o = 16; o; o >>= 1) m = fmaxf(m, __shfl_xor_sync(0xffffffffu, m, o));
        float s = 0.f;
        for (int j = lane; j < KSEL; j += 32) {
            float e = fexp(lg[h][j] - m);
            lg[h][j] = e;
            s += e;
        }
        s = warp_sum(s);
        float inv = 1.f / s;
        for (int j = lane; j < KSEL; j += 32) lg[h][j] *= inv;
    }
    __syncthreads();

    {
        int hh = warp;
        const float* vb = v + (size_t)b * SEQ * EMB + tid;
        const float4* lg4 = (const float4*)&lg[hh][0];
        const int4*   sx4 = (const int4*)sidx;
        float a0 = 0.f, a1 = 0.f, a2 = 0.f, a3 = 0.f;
#pragma unroll 4
        for (int j4 = 0; j4 < KSEL / 4; j4++) {
            float4 p = lg4[j4];
            int4   t = sx4[j4];
            a0 = fmaf(p.x, vb[(size_t)t.x * EMB], a0);
            a1 = fmaf(p.y, vb[(size_t)t.y * EMB], a1);
            a2 = fmaf(p.z, vb[(size_t)t.z * EMB], a2);
            a3 = fmaf(p.w, vb[(size_t)t.w * EMB], a3);
        }
        ctx[(size_t)row * EMB + tid] = (a0 + a1) + (a2 + a3);
    }

    for (int t0 = tid; t0 < SEQ; t0 += 256) rowbuf[t0] = 0.f;
    __syncthreads();
    if (tid < KSEL) {
        float pm = 0.f;
#pragma unroll
        for (int hh = 0; hh < HEADS; hh++) pm += lg[hh][tid];
        rowbuf[sidx[tid]] = pm * 0.125f;
    }
    __syncthreads();
    float4* dst = (float4*)(attn_out + (size_t)row * SEQ);
    const float4* src = (const float4*)rowbuf;
    for (int t0 = tid; t0 < SEQ / 4; t0 += 256) dst[t0] = src[t0];
}

/* ------------ launch: qkv forked onto a side stream during capture ---------- */
extern "C" void kernel_launch(void* const* d_in, const int* in_sizes, int n_in,
                              void* d_out, int out_size)
{
    const float* x  = (const float*)d_in[0];
    const float* Wq = (const float*)d_in[1];
    const float* bq = (const float*)d_in[2];
    const float* Wk = (const float*)d_in[3];
    const float* bk = (const float*)d_in[4];
    const float* Wv = (const float*)d_in[5];
    const float* bv = (const float*)d_in[6];
    const float* Wo = (const float*)d_in[7];
    const float* bo = (const float*)d_in[8];

    float* out  = (float*)d_out;
    float* attn = out + (size_t)BATCH * SEQ * EMB;

    float *scores, *q, *k, *v, *ctx;
    int* idx;
    cudaGetSymbolAddress((void**)&scores, g_scores);
    cudaGetSymbolAddress((void**)&idx,    g_idx);
    cudaGetSymbolAddress((void**)&q,      g_q);
    cudaGetSymbolAddress((void**)&k,      g_k);
    cudaGetSymbolAddress((void**)&v,      g_v);
    cudaGetSymbolAddress((void**)&ctx,    g_ctx);

    cudaStream_t s2 = 0;
    cudaEvent_t evFork = 0, evJoin = 0;
    bool forked = false;
    if (cudaStreamCreateWithFlags(&s2, cudaStreamNonBlocking) == cudaSuccess &&
        cudaEventCreateWithFlags(&evFork, cudaEventDisableTiming) == cudaSuccess &&
        cudaEventCreateWithFlags(&evJoin, cudaEventDisableTiming) == cudaSuccess) {
        forked = (cudaEventRecord(evFork, 0) == cudaSuccess) &&
                 (cudaStreamWaitEvent(s2, evFork, 0) == cudaSuccess);
    }

    if (forked) {
        /* side branch: qkv projections (independent of scores chain) */
        qkv_kernel<<<dim3(6, (BATCH * SEQ) / BM), 256, 0, s2>>>(
            x, Wq, Wk, Wv, bq, bk, bv, q, k, v);
        cudaEventRecord(evJoin, s2);
    }

    /* main chain */
    scores_sym_kernel<<<dim3(136, 1, BATCH), 256>>>(x, scores);
    mirror_kernel<<<dim3(480, 1, BATCH), 256>>>(scores);
    topk_kernel<<<BATCH * SEQ, 256>>>(scores, idx);

    if (forked) {
        cudaStreamWaitEvent(0, evJoin, 0);
    } else {
        /* fallback: serial qkv on the main stream */
        qkv_kernel<<<dim3(6, (BATCH * SEQ) / BM), 256>>>(
            x, Wq, Wk, Wv, bq, bk, bv, q, k, v);
    }

    sparse_attn_kernel<<<BATCH * SEQ, 256>>>(q, k, v, idx, ctx, attn);

    gemm_abt<<<dim3(EMB / BN, (BATCH * SEQ) / BM, 1), 256>>>(
        ctx, Wo, out, bo, EMB, EMB, 1.0f, 0, 0, 0);

    if (evFork) cudaEventDestroy(evFork);
    if (evJoin) cudaEventDestroy(evJoin);
    if (s2) cudaStreamDestroy(s2);
}